// round 17
// baseline (speedup 1.0000x reference)
#include <cuda_runtime.h>

namespace {

constexpr int NBATCH = 256;
constexpr int NTIME  = 512;
constexpr float DT_STEP = 0.01f;

// XLA / Eigen f32 tanh rational approximation (bit-matches XLA's EmitTanh).
__device__ __forceinline__ float xla_tanh(float x) {
  const float CL = 7.90531110763549805f;
  float xc = fmaxf(fminf(x, CL), -CL);
  float x2 = __fmul_rn(xc, xc);
  float p = fmaf(x2, -2.76076847742355e-16f, 2.00018790482477e-13f);
  p = fmaf(x2, p, -8.60467152213735e-11f);
  p = fmaf(x2, p, 5.12229709037114e-08f);
  p = fmaf(x2, p, 1.48572235717979e-05f);
  p = fmaf(x2, p, 6.37261928875436e-04f);
  p = fmaf(x2, p, 4.89352455891786e-03f);
  p = __fmul_rn(xc, p);
  float q = fmaf(x2, 1.19825839466702e-06f, 1.18534705686654e-04f);
  q = fmaf(x2, q, 2.26843463243900e-03f);
  q = fmaf(x2, q, 4.89352518554385e-03f);
  float r = __fdiv_rn(p, q);
  return (fabsf(x) < 0.0004f) ? x : r;
}

// JAX tanh JVP (g + g*ans)*(1-ans), FFMA-contracted then FMUL.
__device__ __forceinline__ float tanh_jvp(float t, float a, float om) {
  return __fmul_rn(fmaf(t, a, t), om);
}

// NEON-style pairwise combine of 4 partial sums: (s0+s1)+(s2+s3)
__device__ __forceinline__ float comb4(const float* s) {
  return __fadd_rn(__fadd_rn(s[0], s[1]), __fadd_rn(s[2], s[3]));
}

// Full 4-lane interleaved dot (single thread), float4 a-loads.
template<int K>
__device__ __forceinline__ float dot4(const float* __restrict__ a,
                                      const float* __restrict__ w,
                                      int stride, int c) {
  float s0 = 0.f, s1 = 0.f, s2 = 0.f, s3 = 0.f;
#pragma unroll
  for (int k = 0; k < K; k += 4) {
    float4 av = *reinterpret_cast<const float4*>(a + k);
    s0 = fmaf(av.x, w[k * stride + c], s0);
    s1 = fmaf(av.y, w[(k + 1) * stride + c], s1);
    s2 = fmaf(av.z, w[(k + 2) * stride + c], s2);
    s3 = fmaf(av.w, w[(k + 3) * stride + c], s3);
  }
  float sv[4] = {s0, s1, s2, s3};
  return comb4(sv);
}

// Sequential K=12 dot, rowA contiguous via float4, colB strided.
__device__ __forceinline__ float seqdot12_rv(const float* __restrict__ rowA,
                                             const float* __restrict__ colB,
                                             int strideB) {
  float a[12];
  *reinterpret_cast<float4*>(a)     = *reinterpret_cast<const float4*>(rowA);
  *reinterpret_cast<float4*>(a + 4) = *reinterpret_cast<const float4*>(rowA + 4);
  *reinterpret_cast<float4*>(a + 8) = *reinterpret_cast<const float4*>(rowA + 8);
  float acc = 0.f;
#pragma unroll
  for (int k = 0; k < 12; ++k) acc = fmaf(a[k], colB[k * strideB], acc);
  return acc;
}

// Sequential K=12 dot, both operands contiguous rows via float4.
__device__ __forceinline__ float seqdot12_rr(const float* __restrict__ rowA,
                                             const float* __restrict__ rowB) {
  float a[12], b[12];
  *reinterpret_cast<float4*>(a)     = *reinterpret_cast<const float4*>(rowA);
  *reinterpret_cast<float4*>(a + 4) = *reinterpret_cast<const float4*>(rowA + 4);
  *reinterpret_cast<float4*>(a + 8) = *reinterpret_cast<const float4*>(rowA + 8);
  *reinterpret_cast<float4*>(b)     = *reinterpret_cast<const float4*>(rowB);
  *reinterpret_cast<float4*>(b + 4) = *reinterpret_cast<const float4*>(rowB + 4);
  *reinterpret_cast<float4*>(b + 8) = *reinterpret_cast<const float4*>(rowB + 8);
  float acc = 0.f;
#pragma unroll
  for (int k = 0; k < 12; ++k) acc = fmaf(a[k], b[k], acc);
  return acc;
}

struct WeightsS {
  float W0[1024]; float b0[64];
  float W1[4096]; float b1[64];
  float W2[2048]; float b2[32];
  float W3[384];  float b3[12];
  float mW0[768]; float mb0[64];
  float mW1[4096]; float mb1[64];
  float mW2[576]; float mb2[12];
  float Qm[144];  float Rm[84];
};

struct Scratch {
  float Ta[768], Tb[768];
  float a1[64], om1[64], a2[64], om2[64], a3[32], om3[32];
  float m1[64], mg1[64], m2[64], mg2[64];
  float x[12], xp[12], u[4], z[12], zp[12];
  float P[144], Pp[144], F[144], FP[144];
  float H[108], HP[108];
  float Mf[192];
  float Kt[108];
};

struct SmemAll { WeightsS w; Scratch ws[2]; };

// Column-parallel fp32 LAPACK sgetf2 + sgetrs on [S | PHt^T]. Bit-identical
// to R15 (proven): lane j owns column j; first-max pivot; rcp scaling.
__device__ __forceinline__ void lu_solve_warp(const float* __restrict__ Mf,
                                              float* __restrict__ Kt, int lane) {
  if (lane >= 21) return;
  const unsigned M21 = 0x001fffffu;
  float r[9];
#pragma unroll
  for (int i = 0; i < 9; ++i) r[i] = Mf[i * 21 + lane];
#pragma unroll
  for (int k = 0; k < 9; ++k) {
    int p = k;
    float best = fabsf(r[k]);
#pragma unroll
    for (int i = k + 1; i < 9; ++i) {
      float v = fabsf(r[i]);
      if (v > best) { best = v; p = i; }
    }
    p = __shfl_sync(M21, p, k);
#pragma unroll
    for (int i = k + 1; i < 9; ++i)
      if (p == i) { float t = r[k]; r[k] = r[i]; r[i] = t; }
    float piv = __shfl_sync(M21, r[k], k);
    float rcp = __fdiv_rn(1.0f, piv);
#pragma unroll
    for (int i = k + 1; i < 9; ++i) {
      float tmp = __fmul_rn(r[i], rcp);
      float li = __shfl_sync(M21, tmp, k);
      if (lane == k) r[i] = li;
      else if (lane > k) r[i] = fmaf(li, -r[k], r[i]);
    }
  }
#pragma unroll
  for (int k = 8; k >= 0; --k) {
    float ukk = __shfl_sync(M21, r[k], k);
    if (lane >= 9) r[k] = __fdiv_rn(r[k], ukk);
#pragma unroll
    for (int i = 0; i < k; ++i) {
      float uik = __shfl_sync(M21, r[i], k);
      if (lane >= 9) r[i] = fmaf(uik, -r[k], r[i]);
    }
  }
  if (lane >= 9) {
#pragma unroll
    for (int k = 0; k < 9; ++k) Kt[k * 12 + (lane - 9)] = r[k];
  }
}

// Warp 12x64x64 GEMM: O[j][c] = epi( sum_k A[j][k] W[k][c] ).
// Lane owns columns {ln, ln+32}; 2 row-groups of 6; 4-lane interleaved
// accumulators + comb4 per output (bit-exact vs dot4).
template<bool TANH>
__device__ __forceinline__ void wmm12x64(const float* __restrict__ A,
                                         const float* __restrict__ W,
                                         const float* __restrict__ act,
                                         const float* __restrict__ omk,
                                         float* __restrict__ O, int ln) {
  const int c0 = ln, c1 = ln + 32;
  const float e0a = act[c0], e0o = omk[c0];
  const float e1a = act[c1], e1o = omk[c1];
#pragma unroll
  for (int g = 0; g < 2; ++g) {
    float acc[6][2][4];
#pragma unroll
    for (int j = 0; j < 6; ++j)
#pragma unroll
      for (int cc = 0; cc < 2; ++cc)
#pragma unroll
        for (int l = 0; l < 4; ++l) acc[j][cc][l] = 0.f;
    for (int k0 = 0; k0 < 64; k0 += 4) {
      float w0[4], w1[4];
#pragma unroll
      for (int l = 0; l < 4; ++l) {
        w0[l] = W[(k0 + l) * 64 + c0];
        w1[l] = W[(k0 + l) * 64 + c1];
      }
#pragma unroll
      for (int j = 0; j < 6; ++j) {
        float av[4];
        *reinterpret_cast<float4*>(av) =
            *reinterpret_cast<const float4*>(A + (g * 6 + j) * 64 + k0);
#pragma unroll
        for (int l = 0; l < 4; ++l) {
          acc[j][0][l] = fmaf(av[l], w0[l], acc[j][0][l]);
          acc[j][1][l] = fmaf(av[l], w1[l], acc[j][1][l]);
        }
      }
    }
#pragma unroll
    for (int j = 0; j < 6; ++j) {
      float f0 = comb4(acc[j][0]);
      float f1 = comb4(acc[j][1]);
      if (TANH) {
        O[(g * 6 + j) * 64 + c0] = tanh_jvp(f0, e0a, e0o);
        O[(g * 6 + j) * 64 + c1] = tanh_jvp(f1, e1a, e1o);
      } else {
        O[(g * 6 + j) * 64 + c0] = (e0o != 0.f) ? f0 : 0.f;
        O[(g * 6 + j) * 64 + c1] = (e1o != 0.f) ? f1 : 0.f;
      }
    }
  }
}

// predict (one warp): consumes s.x, s.P, s.u -> produces s.xp, s.F
__device__ void wpredict(const WeightsS& w, Scratch& s, int ln) {
  // PH1: D1 forward, lane owns cols ln, ln+32 (R11 single-thread form)
#pragma unroll
  for (int cc = 0; cc < 2; ++cc) {
    const int c = ln + 32 * cc;
    float s0 = 0.f, s1 = 0.f, s2 = 0.f, s3 = 0.f;
#pragma unroll
    for (int k = 0; k < 12; k += 4) {
      float4 xv = *reinterpret_cast<const float4*>(s.x + k);
      s0 = fmaf(xv.x, w.W0[k * 64 + c], s0);
      s1 = fmaf(xv.y, w.W0[(k + 1) * 64 + c], s1);
      s2 = fmaf(xv.z, w.W0[(k + 2) * 64 + c], s2);
      s3 = fmaf(xv.w, w.W0[(k + 3) * 64 + c], s3);
    }
    float4 uv = *reinterpret_cast<const float4*>(s.u);
    s0 = fmaf(uv.x, w.W0[12 * 64 + c], s0);
    s1 = fmaf(uv.y, w.W0[13 * 64 + c], s1);
    s2 = fmaf(uv.z, w.W0[14 * 64 + c], s2);
    s3 = fmaf(uv.w, w.W0[15 * 64 + c], s3);
    float sv[4] = {s0, s1, s2, s3};
    float a = xla_tanh(__fadd_rn(comb4(sv), w.b0[c]));
    s.a1[c] = a;
    s.om1[c] = __fsub_rn(1.f, a);
  }
  __syncwarp();
  // PH2: T1 build (24/lane) + D2 layer1 forward (2 cols/lane)
  for (int r = 0; r < 24; ++r) {
    int idx = ln + 32 * r;
    int c = idx & 63;
    s.Ta[idx] = tanh_jvp(w.W0[idx], s.a1[c], s.om1[c]);
  }
#pragma unroll
  for (int cc = 0; cc < 2; ++cc) {
    const int c = ln + 32 * cc;
    float d = dot4<64>(s.a1, w.W1, 64, c);
    float a = xla_tanh(__fadd_rn(d, w.b1[c]));
    s.a2[c] = a;
    s.om2[c] = __fsub_rn(1.f, a);
  }
  __syncwarp();
  // PH3: T2 = jvp(T1 @ W1)
  wmm12x64<true>(s.Ta, w.W1, s.a2, s.om2, s.Tb, ln);
  __syncwarp();
  // PH4: D4 layer2 forward (1 col/lane) + T3 column ln + jvp epilogue
  float aa, oo;
  {
    float d = dot4<64>(s.a2, w.W2, 32, ln);
    aa = xla_tanh(__fadd_rn(d, w.b2[ln]));
    oo = __fsub_rn(1.f, aa);
    s.a3[ln] = aa;
    s.om3[ln] = oo;
  }
  {
    float acc[12][4];
#pragma unroll
    for (int j = 0; j < 12; ++j)
#pragma unroll
      for (int l = 0; l < 4; ++l) acc[j][l] = 0.f;
    for (int k0 = 0; k0 < 64; k0 += 4) {
      float wv[4];
#pragma unroll
      for (int l = 0; l < 4; ++l) wv[l] = w.W2[(k0 + l) * 32 + ln];
#pragma unroll
      for (int j = 0; j < 12; ++j) {
        float tv[4];
        *reinterpret_cast<float4*>(tv) =
            *reinterpret_cast<const float4*>(s.Tb + j * 64 + k0);
#pragma unroll
        for (int l = 0; l < 4; ++l)
          acc[j][l] = fmaf(tv[l], wv[l], acc[j][l]);
      }
    }
    // raw T3 then jvp with THIS column's a3/om3 (k index == column == ln)
#pragma unroll
    for (int j = 0; j < 12; ++j) {
      float f = comb4(acc[j]);
      s.Ta[j * 32 + ln] = tanh_jvp(f, aa, oo);   // jvp'd T3
    }
  }
  __syncwarp();
  // PH5: F (144, 4-5/lane) + xp (lanes 16..27)
  for (int r = 0; r < 5; ++r) {
    int idx = ln + 32 * r;
    if (idx < 144) {
      int i = idx / 12, j = idx % 12;
      const float* tr = s.Ta + j * 32;
      float sv[4] = {0.f, 0.f, 0.f, 0.f};
#pragma unroll
      for (int k = 0; k < 32; k += 4) {
        float tv[4];
        *reinterpret_cast<float4*>(tv) = *reinterpret_cast<const float4*>(tr + k);
#pragma unroll
        for (int l = 0; l < 4; ++l)
          sv[l] = fmaf(tv[l], w.W3[(k + l) * 12 + i], sv[l]);
      }
      float acc = comb4(sv);
      float base = 0.f;
      if (i == j) base = 1.f;
      else if ((i < 3 || (i >= 6 && i < 9)) && j == i + 3) base = DT_STEP;
      s.F[idx] = __fadd_rn(acc, base);
    }
  }
  if (ln >= 16 && ln < 28) {
    const int i = ln - 16;
    float d = dot4<32>(s.a3, w.W3, 12, i);
    float drift = 0.f;
    if (i < 3) drift = s.x[i + 3];
    else if (i >= 6 && i < 9) drift = s.x[i + 3];
    float base = fmaf(DT_STEP, drift, s.x[i]);
    s.xp[i] = __fadd_rn(base, __fadd_rn(d, w.b3[i]));
  }
  __syncwarp();
}

// update (one warp). FIRST skips D6/D7 (Pp preloaded).
template<bool FIRST>
__device__ void wupdate(const WeightsS& w, Scratch& s, int ln,
                        float* __restrict__ est, float* __restrict__ pm,
                        float* __restrict__ cv,
                        const float* __restrict__ cn,
                        const float* __restrict__ mn) {
  // PH6: D6 (FP = F @ P) + M1 (fp64 K=12)
  if (!FIRST) {
    for (int idx = ln; idx < 144; idx += 32) {
      int i = idx / 12, j = idx % 12;
      s.FP[idx] = seqdot12_rv(s.F + i * 12, s.P + j, 12);
    }
  }
#pragma unroll
  for (int cc = 0; cc < 2; ++cc) {
    const int c = ln + 32 * cc;
    double acc = 0.;
#pragma unroll
    for (int k = 0; k < 12; ++k)
      acc = fma((double)s.xp[k], (double)w.mW0[k * 64 + c], acc);
    float pre = __fadd_rn((float)acc, w.mb0[c]);
    s.m1[c] = fmaxf(pre, 0.f);
    s.mg1[c] = pre > 0.f ? 1.f : 0.f;
  }
  __syncwarp();
  // PH7: D7 (Pp = FP F^T + Q) + M2 + mT1 build
  if (!FIRST) {
    for (int idx = ln; idx < 144; idx += 32) {
      int i = idx / 12, j = idx % 12;
      float acc = seqdot12_rr(s.FP + i * 12, s.F + j * 12);
      s.Pp[idx] = __fadd_rn(acc, w.Qm[idx]);
    }
  }
#pragma unroll
  for (int cc = 0; cc < 2; ++cc) {
    const int c = ln + 32 * cc;
    float d = dot4<64>(s.m1, w.mW1, 64, c);
    float pre = __fadd_rn(d, w.mb1[c]);
    s.m2[c] = fmaxf(pre, 0.f);
    s.mg2[c] = pre > 0.f ? 1.f : 0.f;
  }
  for (int r = 0; r < 24; ++r) {
    int idx = ln + 32 * r;
    int c = idx & 63;
    s.Ta[idx] = s.mg1[c] != 0.f ? w.mW0[idx] : 0.f;
  }
  __syncwarp();
  // PH8: mT2 = select(mT1 @ mW1)
  wmm12x64<false>(s.Ta, w.mW1, s.m2, s.mg2, s.Tb, ln);
  __syncwarp();
  // PH9: H (108) + zp (lanes 12..20)
  for (int r = 0; r < 3; ++r) {
    int idx = ln + 32 * r;
    int i = idx / 12, j = idx % 12;
    float f = dot4<64>(s.Tb + j * 64, w.mW2, 9, i);
    s.H[idx] = (i == j) ? __fadd_rn(f, 1.f) : f;
  }
  if (ln < 12) {
    int idx = 96 + ln;
    int i = idx / 12, j = idx % 12;
    float f = dot4<64>(s.Tb + j * 64, w.mW2, 9, i);
    s.H[idx] = (i == j) ? __fadd_rn(f, 1.f) : f;
  } else if (ln < 21) {
    int i = ln - 12;
    float f = dot4<64>(s.m2, w.mW2, 9, i);
    s.zp[i] = __fadd_rn(s.xp[i], __fadd_rn(f, w.mb2[i]));
  }
  __syncwarp();
  // PH10: HP = H @ Pp (108) + PHt -> Mf cols 9..20 (108)
  for (int r = 0; r < 6; ++r) {
    int idx = ln + 32 * r;
    if (idx < 108) {
      int i = idx / 12, j = idx % 12;
      s.HP[idx] = seqdot12_rv(s.H + i * 12, s.Pp + j, 12);
    } else {
      int rr = idx - 108;
      int i = rr / 9, j = rr % 9;
      s.Mf[j * 21 + 9 + i] = seqdot12_rr(s.Pp + i * 12, s.H + j * 12);
    }
  }
  if (ln < 24) {
    int rr = 192 + ln - 108;
    int i = rr / 9, j = rr % 9;
    s.Mf[j * 21 + 9 + i] = seqdot12_rr(s.Pp + i * 12, s.H + j * 12);
  }
  __syncwarp();
  // PH11: S = (HP @ H^T) + R -> Mf cols 0..8
  for (int idx = ln; idx < 81; idx += 32) {
    int i = idx / 9, cc = idx % 9;
    float acc = seqdot12_rr(s.HP + i * 12, s.H + cc * 12);
    s.Mf[i * 21 + cc] = __fadd_rn(acc, w.Rm[i * 9 + cc]);
  }
  __syncwarp();
  // PH12: LU solve
  lu_solve_warp(s.Mf, s.Kt, ln);
  __syncwarp();
  // PH13: E = I - K@H (144) + x_new (lanes 16..27)
  for (int r = 0; r < 5; ++r) {
    int idx = ln + 32 * r;
    if (idx < 144) {
      int i = idx / 12, j = idx % 12;
      float acc = 0.f;
#pragma unroll
      for (int k = 0; k < 9; ++k)
        acc = fmaf(s.Kt[k * 12 + i], s.H[k * 12 + j], acc);
      s.FP[idx] = __fsub_rn((i == j) ? 1.f : 0.f, acc);
    }
  }
  if (ln >= 16 && ln < 28) {
    const int i = ln - 16;
    float acc = 0.f;
#pragma unroll
    for (int k = 0; k < 9; ++k)
      acc = fmaf(s.Kt[k * 12 + i], __fsub_rn(s.z[k], s.zp[k]), acc);
    s.x[i] = __fadd_rn(s.xp[i], acc);
  }
  __syncwarp();
  // PH14: P = E @ Pp (+ store cv directly) + est/pm stores + prefetch u,z
  for (int idx = ln; idx < 144; idx += 32) {
    int i = idx / 12, j = idx % 12;
    float v = seqdot12_rv(s.FP + i * 12, s.Pp + j, 12);
    s.P[idx] = v;
    cv[idx] = v;
  }
  if (ln < 12) est[ln] = s.x[ln];
  else if (ln >= 16 && ln < 25) pm[ln - 16] = s.zp[ln - 16];
  if (ln < 4) s.u[ln] = cn[ln];
  else if (ln >= 4 && ln < 13) s.z[ln - 4] = mn[ln - 4];
  __syncwarp();
}

} // namespace

__global__ __launch_bounds__(64) void ekf_kernel(
    const float* __restrict__ controls,
    const float* __restrict__ measurements,
    const float* __restrict__ init_x,
    const float* __restrict__ init_P,
    const float* __restrict__ Qg,
    const float* __restrict__ Rg,
    const float* __restrict__ dW0, const float* __restrict__ db0,
    const float* __restrict__ dW1, const float* __restrict__ db1,
    const float* __restrict__ dW2, const float* __restrict__ db2,
    const float* __restrict__ dW3, const float* __restrict__ db3,
    const float* __restrict__ mW0p, const float* __restrict__ mb0p,
    const float* __restrict__ mW1p, const float* __restrict__ mb1p,
    const float* __restrict__ mW2p, const float* __restrict__ mb2p,
    float* __restrict__ out)
{
  extern __shared__ float smraw[];
  SmemAll& sm = *reinterpret_cast<SmemAll*>(smraw);
  WeightsS& w = sm.w;
  const int tid = threadIdx.x;
  const int wi = tid >> 5;
  const int ln = tid & 31;
  const int b = blockIdx.x * 2 + wi;
  Scratch& s = sm.ws[wi];

#define CPY(dst, src, n)  for (int i_ = tid; i_ < (n); i_ += 64) (dst)[i_] = (src)[i_]
  CPY(w.W0, dW0, 1024); CPY(w.b0, db0, 64);
  CPY(w.W1, dW1, 4096); CPY(w.b1, db1, 64);
  CPY(w.W2, dW2, 2048); CPY(w.b2, db2, 32);
  CPY(w.W3, dW3, 384);  CPY(w.b3, db3, 12);
  CPY(w.mW0, mW0p, 768);  CPY(w.mb0, mb0p, 64);
  CPY(w.mW1, mW1p, 4096); CPY(w.mb1, mb1p, 64);
  CPY(w.mW2, mW2p, 576);  CPY(w.mb2, mb2p, 9);
  CPY(w.Qm, Qg, 144);
  CPY(w.Rm, Rg, 81);
#undef CPY
  __syncthreads();

  if (ln < 12) s.xp[ln] = init_x[b * 12 + ln];
  for (int i = ln; i < 144; i += 32) s.Pp[i] = init_P[b * 144 + i];
  if (ln < 9) s.z[ln] = measurements[((size_t)b * NTIME + 0) * 9 + ln];
  __syncwarp();

  float* est = out;
  float* pm  = out + (size_t)NBATCH * NTIME * 12;
  float* cv  = out + (size_t)NBATCH * NTIME * 21;

  // t = 0: measurement update only
  {
    size_t o = (size_t)b * NTIME;
    wupdate<true>(w, s, ln, est + o * 12, pm + o * 9, cv + o * 144,
                  controls + (o + 1) * 4, measurements + (o + 1) * 9);
  }

  for (int t = 1; t < NTIME; ++t) {
    wpredict(w, s, ln);
    size_t o = (size_t)b * NTIME + t;
    int tn = (t + 1 < NTIME) ? (t + 1) : t;   // clamped prefetch (deterministic)
    size_t on = (size_t)b * NTIME + tn;
    wupdate<false>(w, s, ln, est + o * 12, pm + o * 9, cv + o * 144,
                   controls + on * 4, measurements + on * 9);
  }
}

extern "C" void kernel_launch(void* const* d_in, const int* in_sizes, int n_in,
                              void* d_out, int out_size) {
  // inputs: 0 states (unused), 1 controls, 2 measurements, 3 initial_state,
  // 4 initial_covariance, 5 Q, 6 R, 7..14 dW/db 0..3, 15..20 mW/mb 0..2
  const float* controls = (const float*)d_in[1];
  const float* meas     = (const float*)d_in[2];
  const float* x0       = (const float*)d_in[3];
  const float* P0       = (const float*)d_in[4];
  const float* Qg       = (const float*)d_in[5];
  const float* Rg       = (const float*)d_in[6];
  const float* dW0 = (const float*)d_in[7];
  const float* db0 = (const float*)d_in[8];
  const float* dW1 = (const float*)d_in[9];
  const float* db1 = (const float*)d_in[10];
  const float* dW2 = (const float*)d_in[11];
  const float* db2 = (const float*)d_in[12];
  const float* dW3 = (const float*)d_in[13];
  const float* db3 = (const float*)d_in[14];
  const float* mW0 = (const float*)d_in[15];
  const float* mb0 = (const float*)d_in[16];
  const float* mW1 = (const float*)d_in[17];
  const float* mb1 = (const float*)d_in[18];
  const float* mW2 = (const float*)d_in[19];
  const float* mb2 = (const float*)d_in[20];
  float* out = (float*)d_out;

  int smem = (int)sizeof(SmemAll);
  cudaFuncSetAttribute(ekf_kernel, cudaFuncAttributeMaxDynamicSharedMemorySize, smem);
  ekf_kernel<<<NBATCH / 2, 64, smem>>>(controls, meas, x0, P0, Qg, Rg,
                                       dW0, db0, dW1, db1, dW2, db2, dW3, db3,
                                       mW0, mb0, mW1, mb1, mW2, mb2, out);
}